// round 12
// baseline (speedup 1.0000x reference)
#include <cuda_runtime.h>
#include <cuda_fp16.h>
#include <cstdint>

#define NROWS   65536
#define IN_DIM  768
#define OUT_DIM 256
#define NLEV    4
#define KCODES  1024

// ---------------- device scratch ----------------
__device__ __align__(256) __half g_a0h[(size_t)NROWS * IN_DIM];   // xn hi; later d1 hi
__device__ __align__(256) __half g_a0m[(size_t)NROWS * IN_DIM];   // xn mid
__device__ __align__(256) __half g_h1h[(size_t)NROWS * OUT_DIM];  // h1 hi; later q hi
__device__ __align__(256) __half g_h1m[(size_t)NROWS * OUT_DIM];  // h1 mid; later q mid
__device__ __align__(256) __half g_resh[(size_t)NROWS * OUT_DIM]; // residual hi (authoritative)
__device__ __align__(256) __half g_resm[(size_t)NROWS * OUT_DIM]; // residual mid
__device__ __align__(256) float  g_qf [(size_t)NROWS * OUT_DIM];
__device__ __align__(256) __half g_wth[1048576];                  // transposed hi weights (packed)
__device__ __align__(256) __half g_wtm[1048576];                  // transposed mid weights
__device__ __align__(256) __half g_cbh[(size_t)NLEV * KCODES * OUT_DIM];
__device__ __align__(256) __half g_cbm[(size_t)NLEV * KCODES * OUT_DIM];
__device__ __align__(256) float  g_scores[(size_t)NROWS * KCODES];  // approx dist scores
__device__ float g_cnorm[NLEV * KCODES];
__device__ float g_cmax[2 * NLEV];   // per level: max ||ch||^2, max ||cm||^2
__device__ float g_accum[8];

// ---------------- helpers ----------------
__device__ __forceinline__ uint32_t smem_u32(const void* p) {
    uint32_t a;
    asm("{ .reg .u64 t; cvta.to.shared.u64 t, %1; cvt.u32.u64 %0, t; }" : "=r"(a) : "l"(p));
    return a;
}
__device__ __forceinline__ void split2h(float v, __half& h, __half& m) {
    h = __float2half_rn(v);
    m = __float2half_rn(v - __half2float(h));
}

#define CP16(dst, src)  asm volatile("cp.async.cg.shared.global [%0], [%1], 16;" :: "r"(dst), "l"(src) : "memory")
#define CP_COMMIT()     asm volatile("cp.async.commit_group;" ::: "memory")
#define CP_WAIT1()      asm volatile("cp.async.wait_group 1;" ::: "memory")

#define LDMX4(r0, r1, r2, r3, addr) \
    asm volatile("ldmatrix.sync.aligned.m8n8.x4.shared.b16 {%0,%1,%2,%3}, [%4];" \
                 : "=r"(r0), "=r"(r1), "=r"(r2), "=r"(r3) : "r"(addr))

__device__ __forceinline__ void mma16816(float* c, const uint32_t* a, const uint32_t* b) {
    asm volatile(
        "mma.sync.aligned.m16n8k16.row.col.f32.f16.f16.f32 "
        "{%0,%1,%2,%3}, {%4,%5,%6,%7}, {%8,%9}, {%0,%1,%2,%3};"
        : "+f"(c[0]), "+f"(c[1]), "+f"(c[2]), "+f"(c[3])
        : "r"(a[0]), "r"(a[1]), "r"(a[2]), "r"(a[3]), "r"(b[0]), "r"(b[1]));
}

__device__ __forceinline__ float blockReduce256(float v, float* sbuf) {
    int tid = threadIdx.x;
#pragma unroll
    for (int o = 16; o > 0; o >>= 1) v += __shfl_down_sync(0xffffffffu, v, o);
    __syncthreads();
    if ((tid & 31) == 0) sbuf[tid >> 5] = v;
    __syncthreads();
    if (tid < 8) {
        v = sbuf[tid];
#pragma unroll
        for (int o = 4; o > 0; o >>= 1) v += __shfl_down_sync(0xffu, v, o);
    }
    return v;
}

// ---------------- small kernels ----------------
__global__ void zero_kernel(float* a, float* cm) {
    if (threadIdx.x < 8) { a[threadIdx.x] = 0.f; cm[threadIdx.x] = 0.f; }
}

__global__ void ln_kernel(const float* __restrict__ x, const float* __restrict__ g,
                          const float* __restrict__ b,
                          __half* __restrict__ xh, __half* __restrict__ xm) {
    __shared__ float sbuf[8];
    __shared__ float mu_s, rstd_s;
    int row = blockIdx.x, tid = threadIdx.x;
    const float* xr = x + (size_t)row * IN_DIM;
    float v0 = xr[tid], v1 = xr[tid + 256], v2 = xr[tid + 512];
    float s = blockReduce256(v0 + v1 + v2, sbuf);
    if (tid == 0) mu_s = s * (1.f / IN_DIM);
    __syncthreads();
    float mu = mu_s;
    float d0 = v0 - mu, d1 = v1 - mu, d2 = v2 - mu;
    float q = blockReduce256(d0 * d0 + d1 * d1 + d2 * d2, sbuf);
    if (tid == 0) rstd_s = rsqrtf(q * (1.f / IN_DIM) + 1e-5f);
    __syncthreads();
    float rstd = rstd_s;
    size_t o = (size_t)row * IN_DIM;
    __half h, m;
    float y0 = d0 * rstd * g[tid]       + b[tid];
    float y1 = d1 * rstd * g[tid + 256] + b[tid + 256];
    float y2 = d2 * rstd * g[tid + 512] + b[tid + 512];
    split2h(y0, h, m); xh[o + tid]       = h; xm[o + tid]       = m;
    split2h(y1, h, m); xh[o + tid + 256] = h; xm[o + tid + 256] = m;
    split2h(y2, h, m); xh[o + tid + 512] = h; xm[o + tid + 512] = m;
}

// transpose + split: W [K,N] row-major -> Bh/Bm [N,K] half
__global__ void wsplit_kernel(const float* __restrict__ W, __half* __restrict__ Bh,
                              __half* __restrict__ Bm, int K, int N) {
    int i = blockIdx.x * 256 + threadIdx.x;
    if (i >= K * N) return;
    int k = i / N, n = i % N;
    __half h, m;
    split2h(W[i], h, m);
    Bh[(size_t)n * K + k] = h;
    Bm[(size_t)n * K + k] = m;
}

__global__ void cbsplit_kernel(const float* __restrict__ cb, __half* __restrict__ h,
                               __half* __restrict__ m) {
    size_t i = (size_t)blockIdx.x * 256 + threadIdx.x;
    __half hh, mm;
    split2h(cb[i], hh, mm);
    h[i] = hh; m[i] = mm;
}

// per-code norms + per-level max split-norms (for rigorous argmin margin)
__global__ void cnorm_kernel(const float* __restrict__ cb, float* __restrict__ cn,
                             float* __restrict__ cmax) {
    int gw = (blockIdx.x * blockDim.x + threadIdx.x) >> 5;
    int lane = threadIdx.x & 31;
    if (gw >= NLEV * KCODES) return;
    const float4* c = (const float4*)(cb + (size_t)gw * OUT_DIM);
    float s = 0.f, sh = 0.f, sm = 0.f;
#pragma unroll
    for (int i = 0; i < 2; i++) {
        float4 v = c[lane + i * 32];
        s += v.x * v.x + v.y * v.y + v.z * v.z + v.w * v.w;
        __half hh, mm;
        float hf, mf;
        split2h(v.x, hh, mm); hf = __half2float(hh); mf = __half2float(mm); sh += hf*hf; sm += mf*mf;
        split2h(v.y, hh, mm); hf = __half2float(hh); mf = __half2float(mm); sh += hf*hf; sm += mf*mf;
        split2h(v.z, hh, mm); hf = __half2float(hh); mf = __half2float(mm); sh += hf*hf; sm += mf*mf;
        split2h(v.w, hh, mm); hf = __half2float(hh); mf = __half2float(mm); sh += hf*hf; sm += mf*mf;
    }
#pragma unroll
    for (int o = 16; o > 0; o >>= 1) {
        s  += __shfl_down_sync(0xffffffffu, s, o);
        sh += __shfl_down_sync(0xffffffffu, sh, o);
        sm += __shfl_down_sync(0xffffffffu, sm, o);
    }
    if (lane == 0) {
        cn[gw] = s;
        int lvl = gw >> 10;
        atomicMax((int*)&cmax[lvl * 2],     __float_as_int(sh));
        atomicMax((int*)&cmax[lvl * 2 + 1], __float_as_int(sm));
    }
}

// candidate scan + exact fp32 rescore + residual/q update. One warp per row.
// Approx scores s_j = cn_j - 2*(rh . ch_j)  (fp32 accum). True-score error bound:
//   err = 2*(||rh||*maxCm + ||rm||*(maxCh+maxCm)) + 2^-21*(||rh||+||rm||)*maxC
//       + 2^-16*||rh||*maxCh + 1e-3
// Candidates { j : s_j <= min_j s_j + 2*err } provably contain the true argmin.
__global__ __launch_bounds__(256)
void candscan_kernel(const float* __restrict__ scores, const float* __restrict__ cn,
                     const float* __restrict__ cb, const float* __restrict__ cmax,
                     __half* __restrict__ resh, __half* __restrict__ resm,
                     float* __restrict__ qf, __half* __restrict__ qh, __half* __restrict__ qm,
                     int mode, float* __restrict__ commit, float* __restrict__ idxf, int lvl) {
    __shared__ float sR[8][OUT_DIM];
    __shared__ float sred[8];
    int wid = threadIdx.x >> 5, lane = threadIdx.x & 31;
    int row = blockIdx.x * 8 + wid;
    size_t ro = (size_t)row * OUT_DIM;

    // load splits, reconstruct r into smem, row norms
    float h2 = 0.f, m2 = 0.f;
#pragma unroll
    for (int i = 0; i < 8; i++) {
        int cc = i * 32 + lane;
        float hv = __half2float(resh[ro + cc]);
        float mv = __half2float(resm[ro + cc]);
        h2 += hv * hv;
        m2 += mv * mv;
        sR[wid][cc] = hv + mv;
    }
#pragma unroll
    for (int o = 16; o > 0; o >>= 1) {
        h2 += __shfl_xor_sync(0xffffffffu, h2, o);
        m2 += __shfl_xor_sync(0xffffffffu, m2, o);
    }
    float nrh = sqrtf(h2), nrm = sqrtf(m2);
    float maxCh = sqrtf(cmax[0]), maxCm = sqrtf(cmax[1]);
    float err = 2.f * (nrh * maxCm + nrm * (maxCh + maxCm))
              + 4.8e-7f * (nrh + nrm) * (maxCh + maxCm)
              + 1.6e-5f * nrh * maxCh
              + 1e-3f;

    const float* srow = scores + (size_t)row * KCODES;
    float mn = 3.4e38f;
#pragma unroll 4
    for (int j = lane; j < KCODES; j += 32) mn = fminf(mn, srow[j]);
#pragma unroll
    for (int o = 16; o > 0; o >>= 1) mn = fminf(mn, __shfl_xor_sync(0xffffffffu, mn, o));
    float thr = mn + 2.f * err;

    float bestS = 3.4e38f;
    int bestI = KCODES;
    for (int j = lane; j < KCODES; j += 32) {
        if (srow[j] <= thr) {
            const float4* crow = (const float4*)(cb + (size_t)j * OUT_DIM);
            float acc = 0.f;
#pragma unroll 8
            for (int k = 0; k < OUT_DIM / 4; k++) {
                float4 cv = crow[k];
                const float* rr = &sR[wid][k * 4];
                acc += rr[0] * cv.x + rr[1] * cv.y + rr[2] * cv.z + rr[3] * cv.w;
            }
            float se = cn[j] - 2.f * acc;
            if (se < bestS || (se == bestS && j < bestI)) { bestS = se; bestI = j; }
        }
    }
#pragma unroll
    for (int o = 16; o > 0; o >>= 1) {
        float os = __shfl_xor_sync(0xffffffffu, bestS, o);
        int oi = __shfl_xor_sync(0xffffffffu, bestI, o);
        if (os < bestS || (os == bestS && oi < bestI)) { bestS = os; bestI = oi; }
    }
    int code = bestI;

    // ---- residual / q update ----
    const float* crow = cb + (size_t)code * OUT_DIM;
    float cpart = 0.f;
#pragma unroll
    for (int i = 0; i < 8; i++) {
        int cc = i * 32 + lane;
        float rv = sR[wid][cc];
        float cv = crow[cc];
        float d = rv - cv;
        if (mode != 2) {
            __half hh, mm;
            split2h(d, hh, mm);
            resh[ro + cc] = hh;
            resm[ro + cc] = mm;
        }
        float qn = (mode == 0) ? cv : (qf[ro + cc] + cv);
        if (mode != 2) {
            qf[ro + cc] = qn;
        } else {
            __half hh, mm;
            split2h(qn, hh, mm);
            qh[ro + cc] = hh;
            qm[ro + cc] = mm;
        }
        cpart += d * d;
    }
#pragma unroll
    for (int o = 16; o > 0; o >>= 1) cpart += __shfl_xor_sync(0xffffffffu, cpart, o);
    if (lane == 0) {
        sred[wid] = cpart;
        if (idxf) idxf[(size_t)row * 4 + lvl] = (float)code;
    }
    __syncthreads();
    if (threadIdx.x == 0) {
        float t = 0.f;
#pragma unroll
        for (int i = 0; i < 8; i++) t += sred[i];
        atomicAdd(commit, t);
    }
}

__global__ void finalize_kernel(const float* __restrict__ a, float* __restrict__ out) {
    out[0] = a[0] * (1.f / ((float)NROWS * IN_DIM))
           + 0.25f * a[1] * (1.f / ((float)NROWS * OUT_DIM));
}

// ---------------- fp16-split GEMM on mma.sync (HMMA) ----------------
// Block tile M=128 x N=128, 256 threads (8 warps), warp tile 32x64, K-step 16,
// 3-stage cp.async pipeline, 2 CTAs/SM.
// Stage layout (24576B): Ah[128r x 48B]=6144 | Am=6144 | Bh[128r x 48B]=6144 | Bm=6144
// NT=3: D = Ah*Bh + Ah*Bm + Am*Bh.  NT=2: D = Ah*Bh + Ah*Bm.  NT=1: D = Ah*Bh.
// MODE 0: relu(D+bias) -> Oh (and Om if non-null)
// MODE 1: c=D+bias -> Oh, Om (hi/mid split only)
// MODE 2: c=D+bias -> Of, partial += (c-aux)^2 -> accum
// MODE 3: scores s = aux[col] - 2*D written to Of[row*Nout + col] (Nout = KCODES)
#define STAGE_B 24576
#define SMEM_MMA (3 * STAGE_B)

template <int MODE, int NT>
__global__ __launch_bounds__(256, 2)
void mma_gemm(int K, int Nout, int nct,
              const __half* __restrict__ Ah, const __half* __restrict__ Am,
              const __half* __restrict__ Bh, const __half* __restrict__ Bm,
              const float* __restrict__ bias,
              float* __restrict__ Of, __half* __restrict__ Oh, __half* __restrict__ Om,
              const float* __restrict__ aux, float* __restrict__ accum) {
    extern __shared__ char dsm[];
    __shared__ float sred[8];
    uint32_t smb = smem_u32(dsm);
    int tid = threadIdx.x, lane = tid & 31, wid = tid >> 5;
    int bm = blockIdx.y * 128;
    int bn0 = blockIdx.x * 128 * nct;
    int wm = (wid & 3) * 32, wn = (wid >> 2) * 64;

    const __half* Abh = Ah + (size_t)bm * K;
    const __half* Abm = Am + (size_t)bm * K;

    int crow = tid >> 1, csub = tid & 1;
    uint32_t cdst = (uint32_t)(crow * 48 + csub * 16);
    size_t csrc = (size_t)crow * K + csub * 8;

    uint32_t aoffA = (uint32_t)((wm + (lane & 15)) * 48 + ((lane >> 4) & 1) * 16);
    uint32_t aoffB = (uint32_t)(12288 + (wn + (lane & 7) + ((lane >> 4) & 1) * 8) * 48
                                + ((lane >> 3) & 1) * 16);

    float partial = 0.f;
    int nk = K >> 4;

    for (int ct = 0; ct < nct; ct++) {
        const __half* Bth = Bh + (size_t)(bn0 + ct * 128) * K;
        const __half* Btm = Bm + (size_t)(bn0 + ct * 128) * K;
        float c[2][8][4];
#pragma unroll
        for (int mt = 0; mt < 2; mt++)
#pragma unroll
            for (int nt = 0; nt < 8; nt++)
#pragma unroll
                for (int k = 0; k < 4; k++) c[mt][nt][k] = 0.f;

        __syncthreads();
#pragma unroll
        for (int s = 0; s < 2; s++) {
            uint32_t sb = smb + s * STAGE_B;
            int ko = s * 16;
            CP16(sb + cdst, (const void*)(Abh + csrc + ko));
            if (NT == 3) CP16(sb + 6144 + cdst, (const void*)(Abm + csrc + ko));
            CP16(sb + 12288 + cdst, (const void*)(Bth + csrc + ko));
            if (NT >= 2) CP16(sb + 18432 + cdst, (const void*)(Btm + csrc + ko));
            CP_COMMIT();
        }

        for (int kt = 0; kt < nk; kt++) {
            int s = kt % 3;
            CP_WAIT1();
            __syncthreads();
            if (kt + 2 < nk) {
                uint32_t sb = smb + ((kt + 2) % 3) * STAGE_B;
                int ko = (kt + 2) * 16;
                CP16(sb + cdst, (const void*)(Abh + csrc + ko));
                if (NT == 3) CP16(sb + 6144 + cdst, (const void*)(Abm + csrc + ko));
                CP16(sb + 12288 + cdst, (const void*)(Bth + csrc + ko));
                if (NT >= 2) CP16(sb + 18432 + cdst, (const void*)(Btm + csrc + ko));
            }
            CP_COMMIT();

            uint32_t sb = smb + s * STAGE_B;
            uint32_t ah[2][4], am[2][4];
#pragma unroll
            for (int mt = 0; mt < 2; mt++) {
                uint32_t ad = sb + aoffA + mt * 768;
                LDMX4(ah[mt][0], ah[mt][1], ah[mt][2], ah[mt][3], ad);
                if (NT == 3)
                    LDMX4(am[mt][0], am[mt][1], am[mt][2], am[mt][3], ad + 6144);
            }
#pragma unroll
            for (int p = 0; p < 4; p++) {
                uint32_t bh[4], bmf[4];
                uint32_t bd = sb + aoffB + p * 768;
                LDMX4(bh[0], bh[1], bh[2], bh[3], bd);
                if (NT >= 2)
                    LDMX4(bmf[0], bmf[1], bmf[2], bmf[3], bd + 6144);
#pragma unroll
                for (int mt = 0; mt < 2; mt++)
#pragma unroll
                    for (int q = 0; q < 2; q++) {
                        int nt = 2 * p + q;
                        mma16816(c[mt][nt], ah[mt], &bh[2 * q]);
                        if (NT >= 2) mma16816(c[mt][nt], ah[mt], &bmf[2 * q]);
                        if (NT == 3) mma16816(c[mt][nt], am[mt], &bh[2 * q]);
                    }
            }
        }

        // ---------------- epilogue ----------------
        if (MODE == 3) {
#pragma unroll
            for (int mt = 0; mt < 2; mt++)
#pragma unroll
                for (int h = 0; h < 2; h++) {
                    int row = bm + wm + mt * 16 + (lane >> 2) + h * 8;
#pragma unroll
                    for (int nt = 0; nt < 8; nt++) {
                        int col = bn0 + ct * 128 + wn + nt * 8 + (lane & 3) * 2;
                        float2 sv;
                        sv.x = aux[col]     - 2.f * c[mt][nt][h * 2 + 0];
                        sv.y = aux[col + 1] - 2.f * c[mt][nt][h * 2 + 1];
                        *(float2*)(Of + (size_t)row * Nout + col) = sv;
                    }
                }
        } else {
#pragma unroll
            for (int mt = 0; mt < 2; mt++)
#pragma unroll
                for (int h = 0; h < 2; h++) {
                    int row = bm + wm + mt * 16 + (lane >> 2) + h * 8;
#pragma unroll
                    for (int nt = 0; nt < 8; nt++) {
                        int col = bn0 + ct * 128 + wn + nt * 8 + (lane & 3) * 2;
                        float v0 = c[mt][nt][h * 2 + 0] + bias[col];
                        float v1 = c[mt][nt][h * 2 + 1] + bias[col + 1];
                        size_t o = (size_t)row * Nout + col;
                        if (MODE == 0) {
                            v0 = fmaxf(v0, 0.f); v1 = fmaxf(v1, 0.f);
                            __half h0, m0, h1x, m1x;
                            split2h(v0, h0, m0); split2h(v1, h1x, m1x);
                            *(__half2*)(Oh + o) = __halves2half2(h0, h1x);
                            if (Om) *(__half2*)(Om + o) = __halves2half2(m0, m1x);
                        } else if (MODE == 1) {
                            __half h0, m0, h1x, m1x;
                            split2h(v0, h0, m0); split2h(v1, h1x, m1x);
                            *(__half2*)(Oh + o) = __halves2half2(h0, h1x);
                            *(__half2*)(Om + o) = __halves2half2(m0, m1x);
                        } else {  // MODE 2
                            Of[o] = v0; Of[o + 1] = v1;
                            float e0 = v0 - aux[o], e1 = v1 - aux[o + 1];
                            partial += e0 * e0 + e1 * e1;
                        }
                    }
                }
        }
    }

    if (MODE == 2) {
        partial = blockReduce256(partial, sred);
        if (tid == 0) atomicAdd(accum, partial);
    }
}

// ---------------- launch ----------------
extern "C" void kernel_launch(void* const* d_in, const int* in_sizes, int n_in,
                              void* d_out, int out_size) {
    const float* x    = (const float*)d_in[0];
    const float* ln_g = (const float*)d_in[1];
    const float* ln_b = (const float*)d_in[2];
    const float* W1   = (const float*)d_in[3];
    const float* b1   = (const float*)d_in[4];
    const float* W2   = (const float*)d_in[5];
    const float* b2   = (const float*)d_in[6];
    const float* Wd1  = (const float*)d_in[7];
    const float* bd1  = (const float*)d_in[8];
    const float* Wd2  = (const float*)d_in[9];
    const float* bd2  = (const float*)d_in[10];
    const float* cbs  = (const float*)d_in[11];
    float* out = (float*)d_out;

    __half *a0h, *a0m, *h1h, *h1m, *resh, *resm, *wth, *wtm, *cbh, *cbm;
    float *qf, *cnorm, *accum, *scores, *cmax;
    cudaGetSymbolAddress((void**)&a0h,  g_a0h);
    cudaGetSymbolAddress((void**)&a0m,  g_a0m);
    cudaGetSymbolAddress((void**)&h1h,  g_h1h);
    cudaGetSymbolAddress((void**)&h1m,  g_h1m);
    cudaGetSymbolAddress((void**)&resh, g_resh);
    cudaGetSymbolAddress((void**)&resm, g_resm);
    cudaGetSymbolAddress((void**)&qf,   g_qf);
    cudaGetSymbolAddress((void**)&wth,  g_wth);
    cudaGetSymbolAddress((void**)&wtm,  g_wtm);
    cudaGetSymbolAddress((void**)&cbh,  g_cbh);
    cudaGetSymbolAddress((void**)&cbm,  g_cbm);
    cudaGetSymbolAddress((void**)&scores, g_scores);
    cudaGetSymbolAddress((void**)&cnorm, g_cnorm);
    cudaGetSymbolAddress((void**)&cmax, g_cmax);
    cudaGetSymbolAddress((void**)&accum, g_accum);

    cudaFuncSetAttribute(mma_gemm<0, 3>, cudaFuncAttributeMaxDynamicSharedMemorySize, SMEM_MMA);
    cudaFuncSetAttribute(mma_gemm<1, 3>, cudaFuncAttributeMaxDynamicSharedMemorySize, SMEM_MMA);
    cudaFuncSetAttribute(mma_gemm<2, 2>, cudaFuncAttributeMaxDynamicSharedMemorySize, SMEM_MMA);
    cudaFuncSetAttribute(mma_gemm<3, 1>, cudaFuncAttributeMaxDynamicSharedMemorySize, SMEM_MMA);

    const size_t reconElems = (size_t)NROWS * IN_DIM;
    size_t reconOff = ((size_t)out_size == reconElems) ? 0 : 1;
    bool fullOut = ((size_t)out_size >= 1 + reconElems + (size_t)NROWS * 4);
    float* idxf = fullOut ? (out + 1 + reconElems) : nullptr;

    // Launch order: enc1 is launch #4 here = ncu's captured launch (offset +2).
    ln_kernel<<<NROWS, 256>>>(x, ln_g, ln_b, a0h, a0m);                        // 1
    wsplit_kernel<<<(768 * 256 + 255) / 256, 256>>>(W1, wth, wtm, 768, 256);   // 2
    zero_kernel<<<1, 32>>>(accum, cmax);                                       // 3
    // 4: encoder GEMM1 (target of ncu capture)
    mma_gemm<0, 3><<<dim3(2, 512), 256, SMEM_MMA>>>(768, 256, 1, a0h, a0m, wth, wtm, b1,
                                                    nullptr, h1h, h1m, nullptr, nullptr);
    wsplit_kernel<<<(256 * 256 + 255) / 256, 256>>>(W2, wth + 196608, wtm + 196608, 256, 256);
    mma_gemm<1, 3><<<dim3(2, 512), 256, SMEM_MMA>>>(256, 256, 1, h1h, h1m,
                                                    wth + 196608, wtm + 196608, b2,
                                                    nullptr, resh, resm, nullptr, nullptr);
    cbsplit_kernel<<<(NLEV * KCODES * OUT_DIM) / 256, 256>>>(cbs, cbh, cbm);
    cnorm_kernel<<<(NLEV * KCODES * 32) / 256, 256>>>(cbs, cnorm, cmax);

    // residual quantization: 1-term approx scores + rigorous candidate rescore/update
    for (int l = 0; l < NLEV; l++) {
        const __half* cbhl = cbh + (size_t)l * KCODES * OUT_DIM;
        mma_gemm<3, 1><<<dim3(8, 512), 256, SMEM_MMA>>>(256, KCODES, 1, resh, resh,
                                                        cbhl, cbhl, nullptr,
                                                        scores, nullptr, nullptr,
                                                        cnorm + l * KCODES, nullptr);
        int mode = (l == 0) ? 0 : ((l == NLEV - 1) ? 2 : 1);
        candscan_kernel<<<NROWS / 8, 256>>>(scores, cnorm + l * KCODES,
                                            cbs + (size_t)l * KCODES * OUT_DIM,
                                            cmax + 2 * l,
                                            resh, resm, qf, h1h, h1m,
                                            mode, accum + 1, idxf, l);
    }

    // decoder: dec1 3-term (d1-mid not stored), dec2 2-term
    wsplit_kernel<<<(256 * 768 + 255) / 256, 256>>>(Wd1, wth + 262144, wtm + 262144, 256, 768);
    mma_gemm<0, 3><<<dim3(6, 512), 256, SMEM_MMA>>>(256, 768, 1, h1h, h1m,
                                                    wth + 262144, wtm + 262144, bd1,
                                                    nullptr, a0h, nullptr, nullptr, nullptr);
    wsplit_kernel<<<(768 * 768 + 255) / 256, 256>>>(Wd2, wth + 458752, wtm + 458752, 768, 768);
    mma_gemm<2, 2><<<dim3(6, 512), 256, SMEM_MMA>>>(768, 768, 1, a0h, a0h,
                                                    wth + 458752, wtm + 458752, bd2,
                                                    out + reconOff, nullptr, nullptr, x, accum);

    if (fullOut) {
        finalize_kernel<<<1, 1>>>(accum, out);
    }
}

// round 13
// speedup vs baseline: 1.0184x; 1.0184x over previous
#include <cuda_runtime.h>
#include <cuda_fp16.h>
#include <cstdint>

#define NROWS   65536
#define IN_DIM  768
#define OUT_DIM 256
#define NLEV    4
#define KCODES  1024

// ---------------- device scratch ----------------
__device__ __align__(256) __half g_a0h[(size_t)NROWS * IN_DIM];   // xn hi; later d1 hi
__device__ __align__(256) __half g_a0m[(size_t)NROWS * IN_DIM];   // xn mid
__device__ __align__(256) __half g_h1h[(size_t)NROWS * OUT_DIM];  // h1 hi; later q hi
__device__ __align__(256) __half g_h1m[(size_t)NROWS * OUT_DIM];  // h1 mid; later q mid
__device__ __align__(256) __half g_resh[(size_t)NROWS * OUT_DIM]; // residual hi (authoritative)
__device__ __align__(256) __half g_resm[(size_t)NROWS * OUT_DIM]; // residual mid
__device__ __align__(256) float  g_qf [(size_t)NROWS * OUT_DIM];
__device__ __align__(256) __half g_wth[1048576];                  // transposed hi weights (packed)
__device__ __align__(256) __half g_wtm[1048576];                  // transposed mid weights
__device__ __align__(256) __half g_cbh[(size_t)NLEV * KCODES * OUT_DIM];
__device__ __align__(256) __half g_cbm[(size_t)NLEV * KCODES * OUT_DIM];
__device__ __align__(256) __half g_scores[(size_t)NROWS * KCODES];  // fp16 approx scores
__device__ __align__(256) float  g_pbV[(size_t)8 * NROWS];          // per-block min partials
__device__ float g_cnorm[NLEV * KCODES];
__device__ float g_cmax[4 * NLEV];   // per level: max||ch||^2, max||cm||^2, max cn
__device__ float g_accum[8];

// ---------------- helpers ----------------
__device__ __forceinline__ uint32_t smem_u32(const void* p) {
    uint32_t a;
    asm("{ .reg .u64 t; cvta.to.shared.u64 t, %1; cvt.u32.u64 %0, t; }" : "=r"(a) : "l"(p));
    return a;
}
__device__ __forceinline__ void split2h(float v, __half& h, __half& m) {
    h = __float2half_rn(v);
    m = __float2half_rn(v - __half2float(h));
}

#define CP16(dst, src)  asm volatile("cp.async.cg.shared.global [%0], [%1], 16;" :: "r"(dst), "l"(src) : "memory")
#define CP_COMMIT()     asm volatile("cp.async.commit_group;" ::: "memory")
#define CP_WAIT1()      asm volatile("cp.async.wait_group 1;" ::: "memory")

#define LDMX4(r0, r1, r2, r3, addr) \
    asm volatile("ldmatrix.sync.aligned.m8n8.x4.shared.b16 {%0,%1,%2,%3}, [%4];" \
                 : "=r"(r0), "=r"(r1), "=r"(r2), "=r"(r3) : "r"(addr))

__device__ __forceinline__ void mma16816(float* c, const uint32_t* a, const uint32_t* b) {
    asm volatile(
        "mma.sync.aligned.m16n8k16.row.col.f32.f16.f16.f32 "
        "{%0,%1,%2,%3}, {%4,%5,%6,%7}, {%8,%9}, {%0,%1,%2,%3};"
        : "+f"(c[0]), "+f"(c[1]), "+f"(c[2]), "+f"(c[3])
        : "r"(a[0]), "r"(a[1]), "r"(a[2]), "r"(a[3]), "r"(b[0]), "r"(b[1]));
}

__device__ __forceinline__ float blockReduce256(float v, float* sbuf) {
    int tid = threadIdx.x;
#pragma unroll
    for (int o = 16; o > 0; o >>= 1) v += __shfl_down_sync(0xffffffffu, v, o);
    __syncthreads();
    if ((tid & 31) == 0) sbuf[tid >> 5] = v;
    __syncthreads();
    if (tid < 8) {
        v = sbuf[tid];
#pragma unroll
        for (int o = 4; o > 0; o >>= 1) v += __shfl_down_sync(0xffu, v, o);
    }
    return v;
}

// ---------------- small kernels ----------------
__global__ void zero_kernel(float* a, float* cm) {
    if (threadIdx.x < 8) a[threadIdx.x] = 0.f;
    if (threadIdx.x < 16) cm[threadIdx.x] = 0.f;
}

__global__ void ln_kernel(const float* __restrict__ x, const float* __restrict__ g,
                          const float* __restrict__ b,
                          __half* __restrict__ xh, __half* __restrict__ xm) {
    __shared__ float sbuf[8];
    __shared__ float mu_s, rstd_s;
    int row = blockIdx.x, tid = threadIdx.x;
    const float* xr = x + (size_t)row * IN_DIM;
    float v0 = xr[tid], v1 = xr[tid + 256], v2 = xr[tid + 512];
    float s = blockReduce256(v0 + v1 + v2, sbuf);
    if (tid == 0) mu_s = s * (1.f / IN_DIM);
    __syncthreads();
    float mu = mu_s;
    float d0 = v0 - mu, d1 = v1 - mu, d2 = v2 - mu;
    float q = blockReduce256(d0 * d0 + d1 * d1 + d2 * d2, sbuf);
    if (tid == 0) rstd_s = rsqrtf(q * (1.f / IN_DIM) + 1e-5f);
    __syncthreads();
    float rstd = rstd_s;
    size_t o = (size_t)row * IN_DIM;
    __half h, m;
    float y0 = d0 * rstd * g[tid]       + b[tid];
    float y1 = d1 * rstd * g[tid + 256] + b[tid + 256];
    float y2 = d2 * rstd * g[tid + 512] + b[tid + 512];
    split2h(y0, h, m); xh[o + tid]       = h; xm[o + tid]       = m;
    split2h(y1, h, m); xh[o + tid + 256] = h; xm[o + tid + 256] = m;
    split2h(y2, h, m); xh[o + tid + 512] = h; xm[o + tid + 512] = m;
}

// transpose + split: W [K,N] row-major -> Bh/Bm [N,K] half
__global__ void wsplit_kernel(const float* __restrict__ W, __half* __restrict__ Bh,
                              __half* __restrict__ Bm, int K, int N) {
    int i = blockIdx.x * 256 + threadIdx.x;
    if (i >= K * N) return;
    int k = i / N, n = i % N;
    __half h, m;
    split2h(W[i], h, m);
    Bh[(size_t)n * K + k] = h;
    Bm[(size_t)n * K + k] = m;
}

__global__ void cbsplit_kernel(const float* __restrict__ cb, __half* __restrict__ h,
                               __half* __restrict__ m) {
    size_t i = (size_t)blockIdx.x * 256 + threadIdx.x;
    __half hh, mm;
    split2h(cb[i], hh, mm);
    h[i] = hh; m[i] = mm;
}

// per-code norms + per-level max split-norms & max cn (for rigorous margin)
__global__ void cnorm_kernel(const float* __restrict__ cb, float* __restrict__ cn,
                             float* __restrict__ cmax) {
    int gw = (blockIdx.x * blockDim.x + threadIdx.x) >> 5;
    int lane = threadIdx.x & 31;
    if (gw >= NLEV * KCODES) return;
    const float4* c = (const float4*)(cb + (size_t)gw * OUT_DIM);
    float s = 0.f, sh = 0.f, sm = 0.f;
#pragma unroll
    for (int i = 0; i < 2; i++) {
        float4 v = c[lane + i * 32];
        s += v.x * v.x + v.y * v.y + v.z * v.z + v.w * v.w;
        __half hh, mm;
        float hf, mf;
        split2h(v.x, hh, mm); hf = __half2float(hh); mf = __half2float(mm); sh += hf*hf; sm += mf*mf;
        split2h(v.y, hh, mm); hf = __half2float(hh); mf = __half2float(mm); sh += hf*hf; sm += mf*mf;
        split2h(v.z, hh, mm); hf = __half2float(hh); mf = __half2float(mm); sh += hf*hf; sm += mf*mf;
        split2h(v.w, hh, mm); hf = __half2float(hh); mf = __half2float(mm); sh += hf*hf; sm += mf*mf;
    }
#pragma unroll
    for (int o = 16; o > 0; o >>= 1) {
        s  += __shfl_down_sync(0xffffffffu, s, o);
        sh += __shfl_down_sync(0xffffffffu, sh, o);
        sm += __shfl_down_sync(0xffffffffu, sm, o);
    }
    if (lane == 0) {
        cn[gw] = s;
        int lvl = gw >> 10;
        atomicMax((int*)&cmax[lvl * 4],     __float_as_int(sh));
        atomicMax((int*)&cmax[lvl * 4 + 1], __float_as_int(sm));
        atomicMax((int*)&cmax[lvl * 4 + 2], __float_as_int(s));
    }
}

// candidate scan + exact warp-cooperative fp32 rescore + residual/q update.
// One warp per row. Stored score ŝ_j = fp16(cn_j - 2*(rh . ch_j)).
// |ŝ_j - s_true_j| <= E; candidates { ŝ_j <= min ŝ + 2E } contain the true argmin.
__global__ __launch_bounds__(256)
void candscan_kernel(const __half* __restrict__ scores, const float* __restrict__ pbV,
                     const float* __restrict__ cn, const float* __restrict__ cb,
                     const float* __restrict__ cmax,
                     __half* __restrict__ resh, __half* __restrict__ resm,
                     float* __restrict__ qf, __half* __restrict__ qh, __half* __restrict__ qm,
                     int mode, float* __restrict__ commit, float* __restrict__ idxf, int lvl) {
    __shared__ float sR[8][OUT_DIM];
    __shared__ float sred[8];
    int wid = threadIdx.x >> 5, lane = threadIdx.x & 31;
    int row = blockIdx.x * 8 + wid;
    size_t ro = (size_t)row * OUT_DIM;

    // load splits, reconstruct r into smem, row split norms
    float h2 = 0.f, m2 = 0.f;
#pragma unroll
    for (int i = 0; i < 8; i++) {
        int cc = i * 32 + lane;
        float hv = __half2float(resh[ro + cc]);
        float mv = __half2float(resm[ro + cc]);
        h2 += hv * hv;
        m2 += mv * mv;
        sR[wid][cc] = hv + mv;
    }
#pragma unroll
    for (int o = 16; o > 0; o >>= 1) {
        h2 += __shfl_xor_sync(0xffffffffu, h2, o);
        m2 += __shfl_xor_sync(0xffffffffu, m2, o);
    }
    float nrh = sqrtf(h2), nrm = sqrtf(m2);
    float maxCh = sqrtf(cmax[0]), maxCm = sqrtf(cmax[1]), cnmax = cmax[2];
    // E: dropped terms + fp32 accum + fp16 quantization + slack
    float E = 2.f * (nrh * maxCm + nrm * (maxCh + maxCm))
            + 1.6e-5f * nrh * maxCh
            + 4.9e-4f * (cnmax + 2.f * (nrh + nrm) * (maxCh + maxCm))
            + 2e-3f;

    // global min of stored fp16 scores via per-block partials
    float mn = 3.4e38f;
    if (lane < 8) mn = pbV[(size_t)lane * NROWS + row];
#pragma unroll
    for (int o = 4; o > 0; o >>= 1) mn = fminf(mn, __shfl_xor_sync(0xffffffffu, mn, o));
    mn = __shfl_sync(0xffffffffu, mn, 0);
    float thr = mn + 2.f * E;

    // candidate scan (fp16 coalesced) + warp-cooperative exact rescore
    const __half* srow = scores + (size_t)row * KCODES;
    float bestS = 3.4e38f;
    int bestI = KCODES;
    for (int base = 0; base < KCODES; base += 32) {
        float sv = __half2float(srow[base + lane]);
        unsigned mask = __ballot_sync(0xffffffffu, sv <= thr);
        while (mask) {
            int b = __ffs(mask) - 1;
            mask &= mask - 1;
            int jc = base + b;
            const float4* cr = (const float4*)(cb + (size_t)jc * OUT_DIM);
            float4 x1 = cr[lane * 2], x2 = cr[lane * 2 + 1];
            const float* rr = &sR[wid][lane * 8];
            float acc = rr[0] * x1.x + rr[1] * x1.y + rr[2] * x1.z + rr[3] * x1.w
                      + rr[4] * x2.x + rr[5] * x2.y + rr[6] * x2.z + rr[7] * x2.w;
#pragma unroll
            for (int o = 16; o > 0; o >>= 1) acc += __shfl_xor_sync(0xffffffffu, acc, o);
            float se = cn[jc] - 2.f * acc;
            if (se < bestS) { bestS = se; bestI = jc; }  // increasing jc -> first-index tiebreak
        }
    }
    int code = bestI;

    // ---- residual / q update ----
    const float* crow = cb + (size_t)code * OUT_DIM;
    float cpart = 0.f;
#pragma unroll
    for (int i = 0; i < 8; i++) {
        int cc = i * 32 + lane;
        float rv = sR[wid][cc];
        float cv = crow[cc];
        float d = rv - cv;
        if (mode != 2) {
            __half hh, mm;
            split2h(d, hh, mm);
            resh[ro + cc] = hh;
            resm[ro + cc] = mm;
        }
        float qn = (mode == 0) ? cv : (qf[ro + cc] + cv);
        if (mode != 2) {
            qf[ro + cc] = qn;
        } else {
            __half hh, mm;
            split2h(qn, hh, mm);
            qh[ro + cc] = hh;
            qm[ro + cc] = mm;
        }
        cpart += d * d;
    }
#pragma unroll
    for (int o = 16; o > 0; o >>= 1) cpart += __shfl_xor_sync(0xffffffffu, cpart, o);
    if (lane == 0) {
        sred[wid] = cpart;
        if (idxf) idxf[(size_t)row * 4 + lvl] = (float)code;
    }
    __syncthreads();
    if (threadIdx.x == 0) {
        float t = 0.f;
#pragma unroll
        for (int i = 0; i < 8; i++) t += sred[i];
        atomicAdd(commit, t);
    }
}

__global__ void finalize_kernel(const float* __restrict__ a, float* __restrict__ out) {
    out[0] = a[0] * (1.f / ((float)NROWS * IN_DIM))
           + 0.25f * a[1] * (1.f / ((float)NROWS * OUT_DIM));
}

// ---------------- fp16-split GEMM on mma.sync (HMMA) ----------------
// Block tile M=128 x N=128, 256 threads (8 warps), warp tile 32x64, K-step 16,
// 3-stage cp.async pipeline, 2 CTAs/SM.
// Stage layout (24576B): Ah[128r x 48B]=6144 | Am=6144 | Bh[128r x 48B]=6144 | Bm=6144
// NT=3: D = Ah*Bh + Ah*Bm + Am*Bh.  NT=2: D = Ah*Bh + Ah*Bm.  NT=1: D = Ah*Bh.
// MODE 0: relu(D+bias) -> Oh (and Om if non-null)
// MODE 1: c=D+bias -> Oh, Om (hi/mid split only)
// MODE 2: c=D+bias -> Of, partial += (c-aux)^2 -> accum
// MODE 3: ŝ = fp16(aux[col]-2D) stored to Oh (fp16, row*Nout+col); per-block min of
//         rounded ŝ written to Of[blockIdx.x*NROWS + bm + tid]
#define STAGE_B 24576
#define SMEM_MMA (3 * STAGE_B)

template <int MODE, int NT>
__global__ __launch_bounds__(256, 2)
void mma_gemm(int K, int Nout, int nct,
              const __half* __restrict__ Ah, const __half* __restrict__ Am,
              const __half* __restrict__ Bh, const __half* __restrict__ Bm,
              const float* __restrict__ bias,
              float* __restrict__ Of, __half* __restrict__ Oh, __half* __restrict__ Om,
              const float* __restrict__ aux, float* __restrict__ accum) {
    extern __shared__ char dsm[];
    __shared__ float sred[8];
    uint32_t smb = smem_u32(dsm);
    int tid = threadIdx.x, lane = tid & 31, wid = tid >> 5;
    int bm = blockIdx.y * 128;
    int bn0 = blockIdx.x * 128 * nct;
    int wm = (wid & 3) * 32, wn = (wid >> 2) * 64;

    const __half* Abh = Ah + (size_t)bm * K;
    const __half* Abm = Am + (size_t)bm * K;

    int crow = tid >> 1, csub = tid & 1;
    uint32_t cdst = (uint32_t)(crow * 48 + csub * 16);
    size_t csrc = (size_t)crow * K + csub * 8;

    uint32_t aoffA = (uint32_t)((wm + (lane & 15)) * 48 + ((lane >> 4) & 1) * 16);
    uint32_t aoffB = (uint32_t)(12288 + (wn + (lane & 7) + ((lane >> 4) & 1) * 8) * 48
                                + ((lane >> 3) & 1) * 16);

    float bestV[4];
#pragma unroll
    for (int i = 0; i < 4; i++) bestV[i] = 3.4e38f;
    float partial = 0.f;
    int nk = K >> 4;

    for (int ct = 0; ct < nct; ct++) {
        const __half* Bth = Bh + (size_t)(bn0 + ct * 128) * K;
        const __half* Btm = Bm + (size_t)(bn0 + ct * 128) * K;
        float c[2][8][4];
#pragma unroll
        for (int mt = 0; mt < 2; mt++)
#pragma unroll
            for (int nt = 0; nt < 8; nt++)
#pragma unroll
                for (int k = 0; k < 4; k++) c[mt][nt][k] = 0.f;

        __syncthreads();
#pragma unroll
        for (int s = 0; s < 2; s++) {
            uint32_t sb = smb + s * STAGE_B;
            int ko = s * 16;
            CP16(sb + cdst, (const void*)(Abh + csrc + ko));
            if (NT == 3) CP16(sb + 6144 + cdst, (const void*)(Abm + csrc + ko));
            CP16(sb + 12288 + cdst, (const void*)(Bth + csrc + ko));
            if (NT >= 2) CP16(sb + 18432 + cdst, (const void*)(Btm + csrc + ko));
            CP_COMMIT();
        }

        for (int kt = 0; kt < nk; kt++) {
            int s = kt % 3;
            CP_WAIT1();
            __syncthreads();
            if (kt + 2 < nk) {
                uint32_t sb = smb + ((kt + 2) % 3) * STAGE_B;
                int ko = (kt + 2) * 16;
                CP16(sb + cdst, (const void*)(Abh + csrc + ko));
                if (NT == 3) CP16(sb + 6144 + cdst, (const void*)(Abm + csrc + ko));
                CP16(sb + 12288 + cdst, (const void*)(Bth + csrc + ko));
                if (NT >= 2) CP16(sb + 18432 + cdst, (const void*)(Btm + csrc + ko));
            }
            CP_COMMIT();

            uint32_t sb = smb + s * STAGE_B;
            uint32_t ah[2][4], am[2][4];
#pragma unroll
            for (int mt = 0; mt < 2; mt++) {
                uint32_t ad = sb + aoffA + mt * 768;
                LDMX4(ah[mt][0], ah[mt][1], ah[mt][2], ah[mt][3], ad);
                if (NT == 3)
                    LDMX4(am[mt][0], am[mt][1], am[mt][2], am[mt][3], ad + 6144);
            }
#pragma unroll
            for (int p = 0; p < 4; p++) {
                uint32_t bh[4], bmf[4];
                uint32_t bd = sb + aoffB + p * 768;
                LDMX4(bh[0], bh[1], bh[2], bh[3], bd);
                if (NT >= 2)
                    LDMX4(bmf[0], bmf[1], bmf[2], bmf[3], bd + 6144);
#pragma unroll
                for (int mt = 0; mt < 2; mt++)
#pragma unroll
                    for (int q = 0; q < 2; q++) {
                        int nt = 2 * p + q;
                        mma16816(c[mt][nt], ah[mt], &bh[2 * q]);
                        if (NT >= 2) mma16816(c[mt][nt], ah[mt], &bmf[2 * q]);
                        if (NT == 3) mma16816(c[mt][nt], am[mt], &bh[2 * q]);
                    }
            }
        }

        // ---------------- epilogue ----------------
        if (MODE == 3) {
#pragma unroll
            for (int mt = 0; mt < 2; mt++)
#pragma unroll
                for (int h = 0; h < 2; h++) {
                    int row = bm + wm + mt * 16 + (lane >> 2) + h * 8;
                    int slot = mt * 2 + h;
#pragma unroll
                    for (int nt = 0; nt < 8; nt++) {
                        int col = bn0 + ct * 128 + wn + nt * 8 + (lane & 3) * 2;
                        float s0 = aux[col]     - 2.f * c[mt][nt][h * 2 + 0];
                        float s1 = aux[col + 1] - 2.f * c[mt][nt][h * 2 + 1];
                        __half q0 = __float2half_rn(s0), q1 = __float2half_rn(s1);
                        *(__half2*)(Oh + (size_t)row * Nout + col) = __halves2half2(q0, q1);
                        bestV[slot] = fminf(bestV[slot],
                                            fminf(__half2float(q0), __half2float(q1)));
                    }
                }
        } else {
#pragma unroll
            for (int mt = 0; mt < 2; mt++)
#pragma unroll
                for (int h = 0; h < 2; h++) {
                    int row = bm + wm + mt * 16 + (lane >> 2) + h * 8;
#pragma unroll
                    for (int nt = 0; nt < 8; nt++) {
                        int col = bn0 + ct * 128 + wn + nt * 8 + (lane & 3) * 2;
                        float v0 = c[mt][nt][h * 2 + 0] + bias[col];
                        float v1 = c[mt][nt][h * 2 + 1] + bias[col + 1];
                        size_t o = (size_t)row * Nout + col;
                        if (MODE == 0) {
                            v0 = fmaxf(v0, 0.f); v1 = fmaxf(v1, 0.f);
                            __half h0, m0, h1x, m1x;
                            split2h(v0, h0, m0); split2h(v1, h1x, m1x);
                            *(__half2*)(Oh + o) = __halves2half2(h0, h1x);
                            if (Om) *(__half2*)(Om + o) = __halves2half2(m0, m1x);
                        } else if (MODE == 1) {
                            __half h0, m0, h1x, m1x;
                            split2h(v0, h0, m0); split2h(v1, h1x, m1x);
                            *(__half2*)(Oh + o) = __halves2half2(h0, h1x);
                            *(__half2*)(Om + o) = __halves2half2(m0, m1x);
                        } else {  // MODE 2
                            Of[o] = v0; Of[o + 1] = v1;
                            float e0 = v0 - aux[o], e1 = v1 - aux[o + 1];
                            partial += e0 * e0 + e1 * e1;
                        }
                    }
                }
        }
    }

    if (MODE == 3) {
        // per-row min partial (value only)
#pragma unroll
        for (int slot = 0; slot < 4; slot++) {
#pragma unroll
            for (int o = 1; o <= 2; o <<= 1)
                bestV[slot] = fminf(bestV[slot], __shfl_xor_sync(0xffffffffu, bestV[slot], o));
        }
        float* sV = (float*)dsm;          // [128][2]
        __syncthreads();
        if ((lane & 3) == 0) {
            int g = wid >> 2;
#pragma unroll
            for (int mt = 0; mt < 2; mt++)
#pragma unroll
                for (int h = 0; h < 2; h++) {
                    int lr = wm + mt * 16 + (lane >> 2) + h * 8;
                    sV[lr * 2 + g] = bestV[mt * 2 + h];
                }
        }
        __syncthreads();
        if (tid < 128)
            Of[(size_t)blockIdx.x * NROWS + bm + tid] = fminf(sV[tid * 2], sV[tid * 2 + 1]);
    }
    if (MODE == 2) {
        partial = blockReduce256(partial, sred);
        if (tid == 0) atomicAdd(accum, partial);
    }
}

// ---------------- launch ----------------
extern "C" void kernel_launch(void* const* d_in, const int* in_sizes, int n_in,
                              void* d_out, int out_size) {
    const float* x    = (const float*)d_in[0];
    const float* ln_g = (const float*)d_in[1];
    const float* ln_b = (const float*)d_in[2];
    const float* W1   = (const float*)d_in[3];
    const float* b1   = (const float*)d_in[4];
    const float* W2   = (const float*)d_in[5];
    const float* b2   = (const float*)d_in[6];
    const float* Wd1  = (const float*)d_in[7];
    const float* bd1  = (const float*)d_in[8];
    const float* Wd2  = (const float*)d_in[9];
    const float* bd2  = (const float*)d_in[10];
    const float* cbs  = (const float*)d_in[11];
    float* out = (float*)d_out;

    __half *a0h, *a0m, *h1h, *h1m, *resh, *resm, *wth, *wtm, *cbh, *cbm, *scores;
    float *qf, *cnorm, *accum, *cmax, *pbV;
    cudaGetSymbolAddress((void**)&a0h,  g_a0h);
    cudaGetSymbolAddress((void**)&a0m,  g_a0m);
    cudaGetSymbolAddress((void**)&h1h,  g_h1h);
    cudaGetSymbolAddress((void**)&h1m,  g_h1m);
    cudaGetSymbolAddress((void**)&resh, g_resh);
    cudaGetSymbolAddress((void**)&resm, g_resm);
    cudaGetSymbolAddress((void**)&qf,   g_qf);
    cudaGetSymbolAddress((void**)&wth,  g_wth);
    cudaGetSymbolAddress((void**)&wtm,  g_wtm);
    cudaGetSymbolAddress((void**)&cbh,  g_cbh);
    cudaGetSymbolAddress((void**)&cbm,  g_cbm);
    cudaGetSymbolAddress((void**)&scores, g_scores);
    cudaGetSymbolAddress((void**)&pbV,  g_pbV);
    cudaGetSymbolAddress((void**)&cnorm, g_cnorm);
    cudaGetSymbolAddress((void**)&cmax, g_cmax);
    cudaGetSymbolAddress((void**)&accum, g_accum);

    cudaFuncSetAttribute(mma_gemm<0, 3>, cudaFuncAttributeMaxDynamicSharedMemorySize, SMEM_MMA);
    cudaFuncSetAttribute(mma_gemm<1, 3>, cudaFuncAttributeMaxDynamicSharedMemorySize, SMEM_MMA);
    cudaFuncSetAttribute(mma_gemm<2, 2>, cudaFuncAttributeMaxDynamicSharedMemorySize, SMEM_MMA);
    cudaFuncSetAttribute(mma_gemm<3, 1>, cudaFuncAttributeMaxDynamicSharedMemorySize, SMEM_MMA);

    const size_t reconElems = (size_t)NROWS * IN_DIM;
    size_t reconOff = ((size_t)out_size == reconElems) ? 0 : 1;
    bool fullOut = ((size_t)out_size >= 1 + reconElems + (size_t)NROWS * 4);
    float* idxf = fullOut ? (out + 1 + reconElems) : nullptr;

    // Launch order: enc1 is launch #4 here = ncu's captured launch (offset +2).
    ln_kernel<<<NROWS, 256>>>(x, ln_g, ln_b, a0h, a0m);                        // 1
    wsplit_kernel<<<(768 * 256 + 255) / 256, 256>>>(W1, wth, wtm, 768, 256);   // 2
    zero_kernel<<<1, 32>>>(accum, cmax);                                       // 3
    // 4: encoder GEMM1 (target of ncu capture)
    mma_gemm<0, 3><<<dim3(2, 512), 256, SMEM_MMA>>>(768, 256, 1, a0h, a0m, wth, wtm, b1,
                                                    nullptr, h1h, h1m, nullptr, nullptr);
    wsplit_kernel<<<(256 * 256 + 255) / 256, 256>>>(W2, wth + 196608, wtm + 196608, 256, 256);
    mma_gemm<1, 3><<<dim3(2, 512), 256, SMEM_MMA>>>(256, 256, 1, h1h, h1m,
                                                    wth + 196608, wtm + 196608, b2,
                                                    nullptr, resh, resm, nullptr, nullptr);
    cbsplit_kernel<<<(NLEV * KCODES * OUT_DIM) / 256, 256>>>(cbs, cbh, cbm);
    cnorm_kernel<<<(NLEV * KCODES * 32) / 256, 256>>>(cbs, cnorm, cmax);

    // residual quantization: 1-term fp16 scores + min partials, then candscan
    for (int l = 0; l < NLEV; l++) {
        const __half* cbhl = cbh + (size_t)l * KCODES * OUT_DIM;
        mma_gemm<3, 1><<<dim3(8, 512), 256, SMEM_MMA>>>(256, KCODES, 1, resh, resh,
                                                        cbhl, cbhl, nullptr,
                                                        pbV, scores, nullptr,
                                                        cnorm + l * KCODES, nullptr);
        int mode = (l == 0) ? 0 : ((l == NLEV - 1) ? 2 : 1);
        candscan_kernel<<<NROWS / 8, 256>>>(scores, pbV, cnorm + l * KCODES,
                                            cbs + (size_t)l * KCODES * OUT_DIM,
                                            cmax + 4 * l,
                                            resh, resm, qf, h1h, h1m,
                                            mode, accum + 1, idxf, l);
    }

    // decoder: dec1 3-term (d1-mid not stored), dec2 2-term
    wsplit_kernel<<<(256 * 768 + 255) / 256, 256>>>(Wd1, wth + 262144, wtm + 262144, 256, 768);
    mma_gemm<0, 3><<<dim3(6, 512), 256, SMEM_MMA>>>(256, 768, 1, h1h, h1m,
                                                    wth + 262144, wtm + 262144, bd1,
                                                    nullptr, a0h, nullptr, nullptr, nullptr);
    wsplit_kernel<<<(768 * 768 + 255) / 256, 256>>>(Wd2, wth + 458752, wtm + 458752, 768, 768);
    mma_gemm<2, 2><<<dim3(6, 512), 256, SMEM_MMA>>>(768, 768, 1, a0h, a0h,
                                                    wth + 458752, wtm + 458752, bd2,
                                                    out + reconOff, nullptr, nullptr, x, accum);

    if (fullOut) {
        finalize_kernel<<<1, 1>>>(accum, out);
    }
}